// round 5
// baseline (speedup 1.0000x reference)
#include <cuda_runtime.h>

#define B_ 2
#define V_ 20000
#define C_ 32
#define NB_ 12
#define KS_ 9
#define OUT_ 32
#define NNODES (B_*V_)
#define KDIM (KS_*C_)     /* 288 */
#define MROWS 40064       /* NNODES padded to multiple of 128 */
#define KP (KDIM/2)       /* 144 c-pairs */

typedef unsigned long long u64;

// Scratch (module-allocated; zero-initialized at load — pad rows of g_y stay 0)
__device__ float g_ep[NNODES * 12];              // exp(ux+c), padded to 12 (pads=0)
__device__ float g_em[NNODES * 12];              // exp(-ux),  padded to 12 (pads=0)
__device__ float g_y[(size_t)MROWS * KDIM];      // 46 MB

#define FMA_F32X2(d, a, b) \
    asm("fma.rn.f32x2 %0, %1, %2, %0;" : "+l"(d) : "l"(a), "l"(b))

__device__ __forceinline__ u64 pack2(float a, float b) {
    u64 r; asm("mov.b64 %0, {%1,%2};" : "=l"(r) : "f"(a), "f"(b)); return r;
}
__device__ __forceinline__ float lo32(u64 v) {
    float a, b; asm("mov.b64 {%0,%1}, %2;" : "=f"(a), "=f"(b) : "l"(v)); return a;
}
__device__ __forceinline__ float hi32(u64 v) {
    float a, b; asm("mov.b64 {%0,%1}, %2;" : "=f"(a), "=f"(b) : "l"(v)); return b;
}
__device__ __forceinline__ float hsum(u64 v) { return lo32(v) + hi32(v); }

// ---------------------------------------------------------------------------
// Kernel 1: ux = x.u ; store E+[k]=exp(ux+c), E-[k]=exp(-ux), 12-padded.
// 4 threads per node, butterfly reduce, float4 stores.
// ---------------------------------------------------------------------------
__global__ void __launch_bounds__(512) k_ux(const float* __restrict__ x,
                                            const float* __restrict__ u,
                                            const float* __restrict__ cvec) {
    __shared__ float u_sm[C_ * KS_];
    __shared__ float c_sm[KS_];
    for (int i = threadIdx.x; i < C_ * KS_; i += 512) u_sm[i] = u[i];
    if (threadIdx.x < KS_) c_sm[threadIdx.x] = cvec[threadIdx.x];
    __syncthreads();

    int t = blockIdx.x * 512 + threadIdx.x;
    int node = t >> 2;
    int qq = t & 3;
    bool valid = node < NNODES;
    int nc = valid ? node : (NNODES - 1);

    const float4* xr = reinterpret_cast<const float4*>(x + (size_t)nc * C_) + qq * 2;
    float4 v0 = xr[0];
    float4 v1 = xr[1];
    float xs[8] = {v0.x, v0.y, v0.z, v0.w, v1.x, v1.y, v1.z, v1.w};

    float acc[KS_];
#pragma unroll
    for (int k = 0; k < KS_; k++) acc[k] = 0.f;
    const int cbase = qq * 8;
#pragma unroll
    for (int j = 0; j < 8; j++)
#pragma unroll
        for (int k = 0; k < KS_; k++)
            acc[k] = fmaf(xs[j], u_sm[(cbase + j) * KS_ + k], acc[k]);
#pragma unroll
    for (int k = 0; k < KS_; k++) acc[k] += __shfl_xor_sync(0xffffffffu, acc[k], 1);
#pragma unroll
    for (int k = 0; k < KS_; k++) acc[k] += __shfl_xor_sync(0xffffffffu, acc[k], 2);

    if (valid && qq < 3) {
        float4 pe, me;
        if (qq < 2) {
            int kb = qq * 4;
            pe = make_float4(__expf(acc[kb] + c_sm[kb]),
                             __expf(acc[kb + 1] + c_sm[kb + 1]),
                             __expf(acc[kb + 2] + c_sm[kb + 2]),
                             __expf(acc[kb + 3] + c_sm[kb + 3]));
            me = make_float4(__expf(-acc[kb]), __expf(-acc[kb + 1]),
                             __expf(-acc[kb + 2]), __expf(-acc[kb + 3]));
        } else {
            pe = make_float4(__expf(acc[8] + c_sm[8]), 0.f, 0.f, 0.f);
            me = make_float4(__expf(-acc[8]), 0.f, 0.f, 0.f);
        }
        reinterpret_cast<float4*>(g_ep + (size_t)node * 12)[qq] = pe;
        reinterpret_cast<float4*>(g_em + (size_t)node * 12)[qq] = me;
    }
}

// ---------------------------------------------------------------------------
// Kernel 2: exp-free attention + neighbor aggregation -> g_y[node][288]
// Warp per node, branchless (q=0 rows for missing neighbors), batched gathers.
// ---------------------------------------------------------------------------
__global__ void __launch_bounds__(256) k_attn(const float* __restrict__ x,
                                              const int* __restrict__ adj) {
    __shared__ float q_sm[8][NB_ * 12];
    const int warp = threadIdx.x >> 5;
    const int lane = threadIdx.x & 31;
    const int node = blockIdx.x * 8 + warp;   // grid = 5000 exact
    const int b = node / V_;
    const int v = node - b * V_;

    int a = (lane < NB_) ? adj[v * NB_ + lane] : 0;
    unsigned nz = __ballot_sync(0xffffffffu, a != 0);
    int deg = __popc(nz);
    float inv_deg = deg ? (1.f / (float)deg) : 0.f;

    if (lane < NB_) {
        float4* qr = reinterpret_cast<float4*>(&q_sm[warp][lane * 12]);
        if (a) {
            const float4* em4 = reinterpret_cast<const float4*>(
                g_em + (size_t)(b * V_ + (a - 1)) * 12);
            const float4* ep4 = reinterpret_cast<const float4*>(
                g_ep + (size_t)node * 12);
            float4 m0 = em4[0], m1 = em4[1], m2 = em4[2];
            float4 p0 = ep4[0], p1 = ep4[1], p2 = ep4[2];
            float q0 = p0.x * m0.x, q1 = p0.y * m0.y, q2 = p0.z * m0.z, q3 = p0.w * m0.w;
            float q4 = p1.x * m1.x, q5 = p1.y * m1.y, q6 = p1.z * m1.z, q7 = p1.w * m1.w;
            float q8 = p2.x * m2.x;
            float s = q0 + q1 + q2 + q3 + q4 + q5 + q6 + q7 + q8;
            float sc = inv_deg / s;
            qr[0] = make_float4(q0 * sc, q1 * sc, q2 * sc, q3 * sc);
            qr[1] = make_float4(q4 * sc, q5 * sc, q6 * sc, q7 * sc);
            qr[2] = make_float4(q8 * sc, 0.f, 0.f, 0.f);
        } else {
            qr[0] = make_float4(0.f, 0.f, 0.f, 0.f);
            qr[1] = make_float4(0.f, 0.f, 0.f, 0.f);
            qr[2] = make_float4(0.f, 0.f, 0.f, 0.f);
        }
    }
    __syncwarp();

    // batched neighbor gathers (MLP=12), q rows already 0 for missing
    float xv[NB_];
#pragma unroll
    for (int n = 0; n < NB_; n++) {
        int an = __shfl_sync(0xffffffffu, a, n);
        int idx = an ? (an - 1) : 0;
        xv[n] = x[((size_t)b * V_ + idx) * C_ + lane];
    }

    u64 acc[5];
#pragma unroll
    for (int t = 0; t < 5; t++) acc[t] = 0ull;

#pragma unroll
    for (int n = 0; n < NB_; n++) {
        u64 xx = pack2(xv[n], xv[n]);
        const u64* q64 = reinterpret_cast<const u64*>(&q_sm[warp][n * 12]);
#pragma unroll
        for (int t = 0; t < 5; t++) FMA_F32X2(acc[t], q64[t], xx);
    }

    float* yo = g_y + (size_t)node * KDIM;
#pragma unroll
    for (int t = 0; t < 4; t++) {
        yo[(2 * t) * C_ + lane] = lo32(acc[t]);
        yo[(2 * t + 1) * C_ + lane] = hi32(acc[t]);
    }
    yo[8 * C_ + lane] = lo32(acc[4]);
}

// ---------------------------------------------------------------------------
// Kernel 3: out = relu(Y @ W2 + b). M=40064, K=288, N=32.
// Thread owns one output row; y streams gmem->regs (c-pairs), W broadcast
// from smem via LDS.128. No smem for y, no syncs in the main loop.
// ---------------------------------------------------------------------------
__global__ void __launch_bounds__(128) k_gemm(const float* __restrict__ W,
                                              const float* __restrict__ bias,
                                              const float* __restrict__ Y,
                                              float* __restrict__ out) {
    __shared__ __align__(16) u64 w_sm[KP * OUT_];   // [kp][o], 36 KB
    __shared__ float b_sm[OUT_];

    const int tid = threadIdx.x;

    // Stage W: kp = k*16+j (pair over c=2j,2j+1 at reduction index i=k*32+c)
    // w_sm[kp*32+o] = ( W[2j][k][o], W[2j+1][k][o] )
    for (int idx = tid; idx < KP * OUT_; idx += 128) {
        int kp = idx >> 5, o = idx & 31;
        int k = kp >> 4, j = kp & 15;
        w_sm[idx] = pack2(W[(2 * j) * KDIM + k * OUT_ + o],
                          W[(2 * j + 1) * KDIM + k * OUT_ + o]);
    }
    if (tid < OUT_) b_sm[tid] = bias[tid];
    __syncthreads();

    const int row = blockIdx.x * 128 + tid;   // < MROWS (pad rows are zeros)
    const float4* ysrc = reinterpret_cast<const float4*>(Y + (size_t)row * KDIM);

    u64 acc[OUT_];
#pragma unroll
    for (int o = 0; o < OUT_; o++) acc[o] = 0ull;

    float4 buf[4];
#pragma unroll
    for (int j = 0; j < 4; j++) buf[j] = ysrc[j];

#pragma unroll 1
    for (int ch = 0; ch < 18; ch++) {         // 18 chunks x 8 kp
        u64 yk[8];
#pragma unroll
        for (int j = 0; j < 4; j++) {
            yk[2 * j]     = pack2(buf[j].x, buf[j].y);
            yk[2 * j + 1] = pack2(buf[j].z, buf[j].w);
        }
        if (ch + 1 < 18) {
#pragma unroll
            for (int j = 0; j < 4; j++) buf[j] = ysrc[(ch + 1) * 4 + j];
        }
        const u64* wrow = &w_sm[(size_t)ch * 8 * OUT_];
#pragma unroll
        for (int p = 0; p < 8; p++) {
#pragma unroll
            for (int o2 = 0; o2 < OUT_ / 2; o2++) {
                ulonglong2 wv = *reinterpret_cast<const ulonglong2*>(
                    &wrow[p * OUT_ + 2 * o2]);                  // broadcast LDS.128
                FMA_F32X2(acc[2 * o2],     yk[p], wv.x);
                FMA_F32X2(acc[2 * o2 + 1], yk[p], wv.y);
            }
        }
    }

    if (row < NNODES) {
        float* dst = out + (size_t)row * OUT_;
#pragma unroll
        for (int o4 = 0; o4 < OUT_ / 4; o4++) {
            float4 ov;
            ov.x = fmaxf(hsum(acc[4 * o4 + 0]) + b_sm[4 * o4 + 0], 0.f);
            ov.y = fmaxf(hsum(acc[4 * o4 + 1]) + b_sm[4 * o4 + 1], 0.f);
            ov.z = fmaxf(hsum(acc[4 * o4 + 2]) + b_sm[4 * o4 + 2], 0.f);
            ov.w = fmaxf(hsum(acc[4 * o4 + 3]) + b_sm[4 * o4 + 3], 0.f);
            reinterpret_cast<float4*>(dst)[o4] = ov;
        }
    }
}

// ---------------------------------------------------------------------------
// Inputs (metadata order): x, W, u, c, b, adj
// ---------------------------------------------------------------------------
extern "C" void kernel_launch(void* const* d_in, const int* in_sizes, int n_in,
                              void* d_out, int out_size) {
    const float* x    = (const float*)d_in[0];
    const float* W    = (const float*)d_in[1];
    const float* u    = (const float*)d_in[2];
    const float* cvec = (const float*)d_in[3];
    const float* bias = (const float*)d_in[4];
    const int*   adj  = (const int*)d_in[5];
    float* out = (float*)d_out;

    float* yptr;
    cudaGetSymbolAddress((void**)&yptr, g_y);

    k_ux<<<(NNODES * 4 + 511) / 512, 512>>>(x, u, cvec);
    k_attn<<<NNODES / 8, 256>>>(x, adj);
    k_gemm<<<MROWS / 128, 128>>>(W, bias, yptr, out);
}